// round 1
// baseline (speedup 1.0000x reference)
#include <cuda_runtime.h>
#include <math.h>

#define MAXN 100000
#define MAXE 1600000
#define HDIM 64

// ---------------- device scratch (no allocations allowed) ----------------
__device__ int   g_is64;
__device__ int   g_row[MAXE];
__device__ int   g_col[MAXE];
__device__ float g_deg[MAXN];          // becomes dinv after rsqrt pass
__device__ float g_y  [(size_t)MAXN * HDIM];
__device__ float g_agg[(size_t)MAXN * HDIM];
__device__ float g_h  [(size_t)MAXN * HDIM];

// ---------------- dtype detection (int32 vs int64 edge_index) ------------
__global__ void detect_kernel(const int* __restrict__ ei) {
    if (threadIdx.x == 0 && blockIdx.x == 0) {
        int is64 = 1;
        for (int i = 1; i < 128; i += 2) {
            if (ei[i] != 0) { is64 = 0; break; }
        }
        g_is64 = is64;
    }
}

__global__ void convert_kernel(const void* __restrict__ ei, int E) {
    int e = blockIdx.x * blockDim.x + threadIdx.x;
    if (e >= E) return;
    if (g_is64) {
        const long long* p = (const long long*)ei;
        g_row[e] = (int)p[e];
        g_col[e] = (int)p[e + E];
    } else {
        const int* p = (const int*)ei;
        g_row[e] = p[e];
        g_col[e] = p[e + E];
    }
}

// ---------------- degree / dinv -------------------------------------------
__global__ void deg_init(int N) {
    int i = blockIdx.x * blockDim.x + threadIdx.x;
    if (i < N) g_deg[i] = 1.0f;   // self loop
}

__global__ void deg_count(int E) {
    int e = blockIdx.x * blockDim.x + threadIdx.x;
    if (e < E) atomicAdd(&g_deg[g_col[e]], 1.0f);
}

__global__ void deg_rsqrt(int N) {
    int i = blockIdx.x * blockDim.x + threadIdx.x;
    if (i < N) g_deg[i] = rsqrtf(g_deg[i]);   // deg >= 1 always
}

// ---------------- GEMM: Y = (X @ W) * dinv, also seeds AGG = Y ------------
// X: [N, K] row-major, W: [K, 64], outputs to g_y and g_agg.
// Block tile 64 rows x 64 cols, 256 threads, thread tile 4x4.
template<int K, bool X_FROM_GH>
__global__ void gemm_scale(const float* __restrict__ Xin,
                           const float* __restrict__ W, int N) {
    const float* __restrict__ X = X_FROM_GH ? g_h : Xin;
    __shared__ float Xs[16][64];
    __shared__ float Ws[16][64];

    int tid = threadIdx.x;
    int ty = tid >> 4;        // 0..15 -> rows ty*4..ty*4+3
    int tx = tid & 15;        // 0..15 -> cols tx*4..tx*4+3
    int row0 = blockIdx.x * 64;

    float acc[4][4] = {};

    int lr  = tid >> 2;           // 0..63 : X load row within tile
    int lkq = (tid & 3) << 2;     // 0,4,8,12 : X load k offset
    int wkr = tid >> 4;           // 0..15 : W load k row
    int wcq = (tid & 15) << 2;    // 0..60 : W load col offset

    for (int kc = 0; kc < K; kc += 16) {
        float4 xv = make_float4(0.f, 0.f, 0.f, 0.f);
        int grow = row0 + lr;
        if (grow < N)
            xv = *(const float4*)(X + (size_t)grow * K + kc + lkq);
        Xs[lkq + 0][lr] = xv.x;
        Xs[lkq + 1][lr] = xv.y;
        Xs[lkq + 2][lr] = xv.z;
        Xs[lkq + 3][lr] = xv.w;

        *(float4*)&Ws[wkr][wcq] =
            *(const float4*)(W + (size_t)(kc + wkr) * 64 + wcq);
        __syncthreads();

        #pragma unroll
        for (int k = 0; k < 16; k++) {
            float4 a = *(const float4*)&Xs[k][ty << 2];
            float4 b = *(const float4*)&Ws[k][tx << 2];
            float av[4] = {a.x, a.y, a.z, a.w};
            float bv[4] = {b.x, b.y, b.z, b.w};
            #pragma unroll
            for (int i = 0; i < 4; i++)
                #pragma unroll
                for (int j = 0; j < 4; j++)
                    acc[i][j] = fmaf(av[i], bv[j], acc[i][j]);
        }
        __syncthreads();
    }

    #pragma unroll
    for (int i = 0; i < 4; i++) {
        int r = row0 + (ty << 2) + i;
        if (r < N) {
            float s = g_deg[r];   // dinv
            float4 v = make_float4(acc[i][0] * s, acc[i][1] * s,
                                   acc[i][2] * s, acc[i][3] * s);
            *(float4*)(g_y   + (size_t)r * 64 + (tx << 2)) = v;
            *(float4*)(g_agg + (size_t)r * 64 + (tx << 2)) = v;
        }
    }
}

// ---------------- edge scatter: agg[col] += y[row] -------------------------
// one thread handles 4 consecutive floats of one edge's 64-wide message
__global__ void scatter_kernel(int E) {
    int idx = blockIdx.x * blockDim.x + threadIdx.x;
    int e = idx >> 4;
    if (e >= E) return;
    int c = (idx & 15) << 2;
    int r = __ldg(&g_row[e]);
    int d = __ldg(&g_col[e]);
    float4 v = *(const float4*)(g_y + (size_t)r * 64 + c);
    float* dst = g_agg + (size_t)d * 64 + c;
    atomicAdd(dst + 0, v.x);
    atomicAdd(dst + 1, v.y);
    atomicAdd(dst + 2, v.z);
    atomicAdd(dst + 3, v.w);
}

// ---------------- finalize: h = relu(dinv * agg + b) -----------------------
__global__ void finalize_kernel(const float* __restrict__ bias, int N) {
    int idx = blockIdx.x * blockDim.x + threadIdx.x;  // over N*16
    if (idx >= N * 16) return;
    int node = idx >> 4;
    int c4 = (idx & 15) << 2;
    float s = g_deg[node];
    float4 v = *(const float4*)(g_agg + (size_t)node * 64 + c4);
    float4 bb = *(const float4*)(bias + c4);
    v.x = fmaxf(fmaf(v.x, s, bb.x), 0.f);
    v.y = fmaxf(fmaf(v.y, s, bb.y), 0.f);
    v.z = fmaxf(fmaf(v.z, s, bb.z), 0.f);
    v.w = fmaxf(fmaf(v.w, s, bb.w), 0.f);
    *(float4*)(g_h + (size_t)node * 64 + c4) = v;
}

// ---------------- fc + sigmoid --------------------------------------------
__global__ void fc_sigmoid(const float* __restrict__ Wfc,
                           const float* __restrict__ bfc,
                           float* __restrict__ out, int N) {
    int gid = blockIdx.x * blockDim.x + threadIdx.x;
    int node = gid >> 5;
    int lane = gid & 31;
    if (node >= N) return;
    const float* hrow = g_h + (size_t)node * 64;
    float v = hrow[lane] * __ldg(&Wfc[lane])
            + hrow[lane + 32] * __ldg(&Wfc[lane + 32]);
    #pragma unroll
    for (int o = 16; o; o >>= 1)
        v += __shfl_down_sync(0xffffffffu, v, o);
    if (lane == 0) {
        float z = v + __ldg(&bfc[0]);
        out[node] = 1.0f / (1.0f + expf(-z));
    }
}

// ---------------- launch ----------------------------------------------------
extern "C" void kernel_launch(void* const* d_in, const int* in_sizes, int n_in,
                              void* d_out, int out_size) {
    const float* x   = (const float*)d_in[0];
    const void*  ei  = d_in[1];
    const float* W1  = (const float*)d_in[2];
    const float* b1  = (const float*)d_in[3];
    const float* W2  = (const float*)d_in[4];
    const float* b2  = (const float*)d_in[5];
    const float* Wfc = (const float*)d_in[6];
    const float* bfc = (const float*)d_in[7];
    float* out = (float*)d_out;

    int N = in_sizes[0] / 128;
    int E = in_sizes[1] / 2;
    if (N > MAXN) N = MAXN;
    if (E > MAXE) E = MAXE;

    const int TB = 256;
    int nb_N  = (N + TB - 1) / TB;
    int nb_E  = (E + TB - 1) / TB;
    int nb_NF = (N * 16 + TB - 1) / TB;     // N*16 threads (float4 per thread)
    int nb_SC = ((long long)E * 16 + TB - 1) / TB;
    int nb_FC = (N * 32 + TB - 1) / TB;
    int nb_GM = (N + 63) / 64;

    detect_kernel<<<1, 32>>>((const int*)ei);
    convert_kernel<<<nb_E, TB>>>(ei, E);
    deg_init<<<nb_N, TB>>>(N);
    deg_count<<<nb_E, TB>>>(E);
    deg_rsqrt<<<nb_N, TB>>>(N);

    // layer 1
    gemm_scale<128, false><<<nb_GM, 256>>>(x, W1, N);
    scatter_kernel<<<nb_SC, TB>>>(E);
    finalize_kernel<<<nb_NF, TB>>>(b1, N);

    // layer 2
    gemm_scale<64, true><<<nb_GM, 256>>>(nullptr, W2, N);
    scatter_kernel<<<nb_SC, TB>>>(E);
    finalize_kernel<<<nb_NF, TB>>>(b2, N);

    // head
    fc_sigmoid<<<nb_FC, TB>>>(Wfc, bfc, out, N);
}

// round 2
// speedup vs baseline: 2.1356x; 2.1356x over previous
#include <cuda_runtime.h>
#include <math.h>

#define MAXN 100000
#define MAXE 1600000
#define HDIM 64

// ---------------- device scratch (no allocations allowed) ----------------
__device__ int   g_is64;
__device__ int   g_row [MAXE];   // edge source
__device__ int   g_cole[MAXE];   // edge dest
__device__ int   g_srcs[MAXE];   // sources sorted by dest (CSR payload)
__device__ int   g_degi[MAXN];   // in-degree (excl self loop)
__device__ int   g_off [MAXN];   // CSR offsets (exclusive prefix of degi)
__device__ int   g_cur [MAXN];   // placement cursors
__device__ float g_dinv[MAXN];
__device__ float g_y  [(size_t)MAXN * HDIM];
__device__ float g_h  [(size_t)MAXN * HDIM];

// ---------------- dtype detection (int32 vs int64 edge_index) ------------
__global__ void detect_kernel(const int* __restrict__ ei) {
    if (threadIdx.x == 0 && blockIdx.x == 0) {
        int is64 = 1;
        for (int i = 1; i < 128; i += 2)
            if (ei[i] != 0) { is64 = 0; break; }
        g_is64 = is64;
    }
}

__global__ void zero_deg(int N) {
    int i = blockIdx.x * blockDim.x + threadIdx.x;
    if (i < N) g_degi[i] = 0;
}

// convert + degree histogram in one pass
__global__ void convert_kernel(const void* __restrict__ ei, int E) {
    int e = blockIdx.x * blockDim.x + threadIdx.x;
    if (e >= E) return;
    int r, c;
    if (g_is64) {
        const long long* p = (const long long*)ei;
        r = (int)p[e]; c = (int)p[e + E];
    } else {
        const int* p = (const int*)ei;
        r = p[e]; c = p[e + E];
    }
    g_row[e] = r;
    g_cole[e] = c;
    atomicAdd(&g_degi[c], 1);
}

// single-block hierarchical exclusive scan of g_degi -> g_off, g_cur
__global__ void scan_kernel(int N) {
    __shared__ int warpsum[32];
    __shared__ int s_carry;
    if (threadIdx.x == 0) s_carry = 0;
    __syncthreads();
    int lane = threadIdx.x & 31, wid = threadIdx.x >> 5;

    for (int base = 0; base < N; base += 4096) {
        int idx = base + threadIdx.x * 4;
        int4 v = make_int4(0, 0, 0, 0);
        if (idx + 3 < N) v = *(const int4*)(g_degi + idx);
        else {
            if (idx     < N) v.x = g_degi[idx];
            if (idx + 1 < N) v.y = g_degi[idx + 1];
            if (idx + 2 < N) v.z = g_degi[idx + 2];
            if (idx + 3 < N) v.w = g_degi[idx + 3];
        }
        int s0 = v.x, s1 = s0 + v.y, s2 = s1 + v.z, s3 = s2 + v.w;
        int sc = s3;  // warp inclusive scan of per-thread sums
        #pragma unroll
        for (int o = 1; o < 32; o <<= 1) {
            int t = __shfl_up_sync(0xffffffffu, sc, o);
            if (lane >= o) sc += t;
        }
        if (lane == 31) warpsum[wid] = sc;
        __syncthreads();
        if (wid == 0) {
            int ws = warpsum[lane];
            int wsc = ws;
            #pragma unroll
            for (int o = 1; o < 32; o <<= 1) {
                int t = __shfl_up_sync(0xffffffffu, wsc, o);
                if (lane >= o) wsc += t;
            }
            warpsum[lane] = wsc - ws;  // exclusive
        }
        __syncthreads();
        int carry = s_carry + warpsum[wid] + (sc - s3);  // thread's exclusive prefix
        int e0 = carry, e1 = carry + s0, e2 = carry + s1, e3 = carry + s2;
        if (idx     < N) { g_off[idx]     = e0; g_cur[idx]     = e0; }
        if (idx + 1 < N) { g_off[idx + 1] = e1; g_cur[idx + 1] = e1; }
        if (idx + 2 < N) { g_off[idx + 2] = e2; g_cur[idx + 2] = e2; }
        if (idx + 3 < N) { g_off[idx + 3] = e3; g_cur[idx + 3] = e3; }
        __syncthreads();
        if (threadIdx.x == 1023) s_carry = e3 + v.w;
        __syncthreads();
    }
}

// place sources into CSR slots (1 int atomic per edge)
__global__ void place_kernel(int E) {
    int e = blockIdx.x * blockDim.x + threadIdx.x;
    if (e >= E) return;
    int c = g_cole[e];
    int pos = atomicAdd(&g_cur[c], 1);
    g_srcs[pos] = g_row[e];
}

__global__ void dinv_kernel(int N) {
    int i = blockIdx.x * blockDim.x + threadIdx.x;
    if (i < N) g_dinv[i] = rsqrtf((float)(g_degi[i] + 1));
}

// ---------------- GEMM: Y = (X @ W) * dinv ---------------------------------
// X: [N, K] row-major, W: [K, 64]. Block 64x64, 256 threads, thread tile 4x4.
template<int K, bool X_FROM_GH>
__global__ void gemm_scale(const float* __restrict__ Xin,
                           const float* __restrict__ W, int N) {
    const float* __restrict__ X = X_FROM_GH ? g_h : Xin;
    __shared__ float Xs[16][64];
    __shared__ float Ws[16][64];

    int tid = threadIdx.x;
    int ty = tid >> 4;
    int tx = tid & 15;
    int row0 = blockIdx.x * 64;

    float acc[4][4] = {};

    int lr  = tid >> 2;
    int lkq = (tid & 3) << 2;
    int wkr = tid >> 4;
    int wcq = (tid & 15) << 2;

    for (int kc = 0; kc < K; kc += 16) {
        float4 xv = make_float4(0.f, 0.f, 0.f, 0.f);
        int grow = row0 + lr;
        if (grow < N)
            xv = *(const float4*)(X + (size_t)grow * K + kc + lkq);
        Xs[lkq + 0][lr] = xv.x;
        Xs[lkq + 1][lr] = xv.y;
        Xs[lkq + 2][lr] = xv.z;
        Xs[lkq + 3][lr] = xv.w;

        *(float4*)&Ws[wkr][wcq] =
            *(const float4*)(W + (size_t)(kc + wkr) * 64 + wcq);
        __syncthreads();

        #pragma unroll
        for (int k = 0; k < 16; k++) {
            float4 a = *(const float4*)&Xs[k][ty << 2];
            float4 b = *(const float4*)&Ws[k][tx << 2];
            float av[4] = {a.x, a.y, a.z, a.w};
            float bv[4] = {b.x, b.y, b.z, b.w};
            #pragma unroll
            for (int i = 0; i < 4; i++)
                #pragma unroll
                for (int j = 0; j < 4; j++)
                    acc[i][j] = fmaf(av[i], bv[j], acc[i][j]);
        }
        __syncthreads();
    }

    #pragma unroll
    for (int i = 0; i < 4; i++) {
        int r = row0 + (ty << 2) + i;
        if (r < N) {
            float s = g_dinv[r];
            float4 v = make_float4(acc[i][0] * s, acc[i][1] * s,
                                   acc[i][2] * s, acc[i][3] * s);
            *(float4*)(g_y + (size_t)r * 64 + (tx << 2)) = v;
        }
    }
}

// ---------------- warp-per-node aggregation (no atomics) -------------------
// acc = y[node] (self) + sum_{s in CSR(node)} y[s]; then
//   !FINAL: g_h[node] = relu(dinv*acc + bias)
//   FINAL : out[node] = sigmoid(dot(relu(dinv*acc + bias), Wfc) + bfc)
template<bool FINAL>
__global__ void aggregate_kernel(const float* __restrict__ bias,
                                 const float* __restrict__ Wfc,
                                 const float* __restrict__ bfc,
                                 float* __restrict__ out, int N) {
    int node = blockIdx.x * 8 + (threadIdx.x >> 5);
    if (node >= N) return;
    int lane = threadIdx.x & 31;

    int beg = g_off[node];
    int cnt = g_degi[node];

    const float* yp = g_y + (size_t)node * 64 + lane * 2;
    float2 acc = *(const float2*)yp;  // self loop (already dinv-scaled)

    int i = 0;
    for (; i + 1 < cnt; i += 2) {
        int s0 = __ldg(&g_srcs[beg + i]);
        int s1 = __ldg(&g_srcs[beg + i + 1]);
        float2 v0 = *(const float2*)(g_y + (size_t)s0 * 64 + lane * 2);
        float2 v1 = *(const float2*)(g_y + (size_t)s1 * 64 + lane * 2);
        acc.x += v0.x + v1.x;
        acc.y += v0.y + v1.y;
    }
    if (i < cnt) {
        int s0 = __ldg(&g_srcs[beg + i]);
        float2 v0 = *(const float2*)(g_y + (size_t)s0 * 64 + lane * 2);
        acc.x += v0.x;
        acc.y += v0.y;
    }

    float dv = g_dinv[node];
    float hx = fmaxf(fmaf(acc.x, dv, __ldg(&bias[lane * 2])), 0.f);
    float hy = fmaxf(fmaf(acc.y, dv, __ldg(&bias[lane * 2 + 1])), 0.f);

    if (!FINAL) {
        *(float2*)(g_h + (size_t)node * 64 + lane * 2) = make_float2(hx, hy);
    } else {
        float v = hx * __ldg(&Wfc[lane * 2]) + hy * __ldg(&Wfc[lane * 2 + 1]);
        #pragma unroll
        for (int o = 16; o; o >>= 1)
            v += __shfl_down_sync(0xffffffffu, v, o);
        if (lane == 0) {
            float z = v + __ldg(&bfc[0]);
            out[node] = 1.0f / (1.0f + expf(-z));
        }
    }
}

// ---------------- launch ----------------------------------------------------
extern "C" void kernel_launch(void* const* d_in, const int* in_sizes, int n_in,
                              void* d_out, int out_size) {
    const float* x   = (const float*)d_in[0];
    const void*  ei  = d_in[1];
    const float* W1  = (const float*)d_in[2];
    const float* b1  = (const float*)d_in[3];
    const float* W2  = (const float*)d_in[4];
    const float* b2  = (const float*)d_in[5];
    const float* Wfc = (const float*)d_in[6];
    const float* bfc = (const float*)d_in[7];
    float* out = (float*)d_out;

    int N = in_sizes[0] / 128;
    int E = in_sizes[1] / 2;
    if (N > MAXN) N = MAXN;
    if (E > MAXE) E = MAXE;

    const int TB = 256;
    int nb_N  = (N + TB - 1) / TB;
    int nb_E  = (E + TB - 1) / TB;
    int nb_GM = (N + 63) / 64;
    int nb_AG = (N + 7) / 8;

    detect_kernel<<<1, 32>>>((const int*)ei);
    zero_deg<<<nb_N, TB>>>(N);
    convert_kernel<<<nb_E, TB>>>(ei, E);
    scan_kernel<<<1, 1024>>>(N);
    place_kernel<<<nb_E, TB>>>(E);
    dinv_kernel<<<nb_N, TB>>>(N);

    // layer 1
    gemm_scale<128, false><<<nb_GM, 256>>>(x, W1, N);
    aggregate_kernel<false><<<nb_AG, 256>>>(b1, nullptr, nullptr, nullptr, N);

    // layer 2
    gemm_scale<64, true><<<nb_GM, 256>>>(nullptr, W2, N);
    aggregate_kernel<true><<<nb_AG, 256>>>(b2, Wfc, bfc, out, N);
}

// round 3
// speedup vs baseline: 2.8108x; 1.3162x over previous
#include <cuda_runtime.h>
#include <math.h>

#define MAXN 100000
#define MAXE 1600000
#define HDIM 64
#define SCAN_TILE 4096

// ---------------- device scratch (no allocations allowed) ----------------
__device__ int   g_is64;
__device__ int   g_row [MAXE];   // edge source
__device__ int   g_cole[MAXE];   // edge dest
__device__ int   g_srcs[MAXE];   // sources sorted by dest (CSR payload)
__device__ int   g_degi[MAXN];   // in-degree (excl self loop)
__device__ int   g_off [MAXN];   // CSR offsets (exclusive prefix of degi)
__device__ int   g_cur [MAXN];   // placement cursors
__device__ int   g_bsum[64];     // per-block scan sums
__device__ float g_dinv[MAXN];
__device__ float g_y  [(size_t)MAXN * HDIM];
__device__ float g_h  [(size_t)MAXN * HDIM];

// ---------------- dtype detection (int32 vs int64 edge_index) ------------
__global__ void detect_kernel(const int* __restrict__ ei) {
    if (threadIdx.x == 0 && blockIdx.x == 0) {
        int is64 = 1;
        for (int i = 1; i < 128; i += 2)
            if (ei[i] != 0) { is64 = 0; break; }
        g_is64 = is64;
    }
}

__global__ void zero_deg(int N) {
    int i = blockIdx.x * blockDim.x + threadIdx.x;
    if (i < N) g_degi[i] = 0;
}

// convert + degree histogram in one pass
__global__ void convert_kernel(const void* __restrict__ ei, int E) {
    int e = blockIdx.x * blockDim.x + threadIdx.x;
    if (e >= E) return;
    int r, c;
    if (g_is64) {
        const long long* p = (const long long*)ei;
        r = (int)p[e]; c = (int)p[e + E];
    } else {
        const int* p = (const int*)ei;
        r = p[e]; c = p[e + E];
    }
    g_row[e] = r;
    g_cole[e] = c;
    atomicAdd(&g_degi[c], 1);
}

// ---------------- multi-block exclusive scan ------------------------------
// pass 1: per-block exclusive scan (4096 elems/block), block total -> g_bsum
__global__ void scan_pass1(int N) {
    __shared__ int warpsum[32];
    int lane = threadIdx.x & 31, wid = threadIdx.x >> 5;
    int idx = blockIdx.x * SCAN_TILE + threadIdx.x * 4;

    int4 v = make_int4(0, 0, 0, 0);
    if (idx + 3 < N) v = *(const int4*)(g_degi + idx);
    else {
        if (idx     < N) v.x = g_degi[idx];
        if (idx + 1 < N) v.y = g_degi[idx + 1];
        if (idx + 2 < N) v.z = g_degi[idx + 2];
        if (idx + 3 < N) v.w = g_degi[idx + 3];
    }
    int s0 = v.x, s1 = s0 + v.y, s2 = s1 + v.z, s3 = s2 + v.w;
    int sc = s3;
    #pragma unroll
    for (int o = 1; o < 32; o <<= 1) {
        int t = __shfl_up_sync(0xffffffffu, sc, o);
        if (lane >= o) sc += t;
    }
    if (lane == 31) warpsum[wid] = sc;
    __syncthreads();
    if (wid == 0) {
        int ws = warpsum[lane];
        int wsc = ws;
        #pragma unroll
        for (int o = 1; o < 32; o <<= 1) {
            int t = __shfl_up_sync(0xffffffffu, wsc, o);
            if (lane >= o) wsc += t;
        }
        warpsum[lane] = wsc - ws;  // exclusive warp prefix
        if (lane == 31) g_bsum[blockIdx.x] = wsc;  // block total
    }
    __syncthreads();
    int carry = warpsum[wid] + (sc - s3);
    if (idx     < N) g_off[idx]     = carry;
    if (idx + 1 < N) g_off[idx + 1] = carry + s0;
    if (idx + 2 < N) g_off[idx + 2] = carry + s1;
    if (idx + 3 < N) g_off[idx + 3] = carry + s2;
}

// pass 2: exclusive scan of block sums (<= 32 blocks for N<=128k... use 64)
__global__ void scan_pass2(int nblk) {
    int lane = threadIdx.x;  // 64 threads
    __shared__ int sh[64];
    int v = (lane < nblk) ? g_bsum[lane] : 0;
    sh[lane] = v;
    __syncthreads();
    // simple serial-ish scan via one thread is fine for <=64 values, but do
    // a Hillis-Steele in smem
    int acc = v;
    for (int o = 1; o < 64; o <<= 1) {
        int t = (lane >= o) ? sh[lane - o] : 0;
        __syncthreads();
        acc += t;
        sh[lane] = acc;
        __syncthreads();
    }
    if (lane < nblk) g_bsum[lane] = acc - v;  // exclusive
}

// pass 3: add block offsets, init cursors
__global__ void scan_pass3(int N) {
    int idx = (blockIdx.x * blockDim.x + threadIdx.x) * 4;
    if (idx >= N) return;
    int add = g_bsum[idx / SCAN_TILE];   // 4 consecutive always in same tile
    if (idx + 3 < N) {
        int4 v = *(const int4*)(g_off + idx);
        v.x += add; v.y += add; v.z += add; v.w += add;
        *(int4*)(g_off + idx) = v;
        *(int4*)(g_cur + idx) = v;
    } else {
        for (int k = 0; k < 4 && idx + k < N; k++) {
            int v = g_off[idx + k] + add;
            g_off[idx + k] = v;
            g_cur[idx + k] = v;
        }
    }
}

// place sources into CSR slots (1 int atomic per edge)
__global__ void place_kernel(int E) {
    int e = blockIdx.x * blockDim.x + threadIdx.x;
    if (e >= E) return;
    int c = g_cole[e];
    int pos = atomicAdd(&g_cur[c], 1);
    g_srcs[pos] = g_row[e];
}

__global__ void dinv_kernel(int N) {
    int i = blockIdx.x * blockDim.x + threadIdx.x;
    if (i < N) g_dinv[i] = rsqrtf((float)(g_degi[i] + 1));
}

// ---------------- GEMM: Y = (X @ W) * dinv ---------------------------------
// X: [N, K] row-major, W: [K, 64]. Block 64x64, 256 threads, thread tile 4x4.
template<int K, bool X_FROM_GH>
__global__ void gemm_scale(const float* __restrict__ Xin,
                           const float* __restrict__ W, int N) {
    const float* __restrict__ X = X_FROM_GH ? g_h : Xin;
    __shared__ float Xs[16][64];
    __shared__ float Ws[16][64];

    int tid = threadIdx.x;
    int ty = tid >> 4;
    int tx = tid & 15;
    int row0 = blockIdx.x * 64;

    float acc[4][4] = {};

    int lr  = tid >> 2;
    int lkq = (tid & 3) << 2;
    int wkr = tid >> 4;
    int wcq = (tid & 15) << 2;

    for (int kc = 0; kc < K; kc += 16) {
        float4 xv = make_float4(0.f, 0.f, 0.f, 0.f);
        int grow = row0 + lr;
        if (grow < N)
            xv = *(const float4*)(X + (size_t)grow * K + kc + lkq);
        Xs[lkq + 0][lr] = xv.x;
        Xs[lkq + 1][lr] = xv.y;
        Xs[lkq + 2][lr] = xv.z;
        Xs[lkq + 3][lr] = xv.w;

        *(float4*)&Ws[wkr][wcq] =
            *(const float4*)(W + (size_t)(kc + wkr) * 64 + wcq);
        __syncthreads();

        #pragma unroll
        for (int k = 0; k < 16; k++) {
            float4 a = *(const float4*)&Xs[k][ty << 2];
            float4 b = *(const float4*)&Ws[k][tx << 2];
            float av[4] = {a.x, a.y, a.z, a.w};
            float bv[4] = {b.x, b.y, b.z, b.w};
            #pragma unroll
            for (int i = 0; i < 4; i++)
                #pragma unroll
                for (int j = 0; j < 4; j++)
                    acc[i][j] = fmaf(av[i], bv[j], acc[i][j]);
        }
        __syncthreads();
    }

    #pragma unroll
    for (int i = 0; i < 4; i++) {
        int r = row0 + (ty << 2) + i;
        if (r < N) {
            float s = g_dinv[r];
            float4 v = make_float4(acc[i][0] * s, acc[i][1] * s,
                                   acc[i][2] * s, acc[i][3] * s);
            *(float4*)(g_y + (size_t)r * 64 + (tx << 2)) = v;
        }
    }
}

// ---------------- warp-per-node aggregation (no atomics) -------------------
template<bool FINAL>
__global__ void aggregate_kernel(const float* __restrict__ bias,
                                 const float* __restrict__ Wfc,
                                 const float* __restrict__ bfc,
                                 float* __restrict__ out, int N) {
    int node = blockIdx.x * 8 + (threadIdx.x >> 5);
    if (node >= N) return;
    int lane = threadIdx.x & 31;

    int beg = g_off[node];
    int cnt = g_degi[node];

    const float* yp = g_y + (size_t)node * 64 + lane * 2;
    float2 acc = *(const float2*)yp;  // self loop (already dinv-scaled)

    int i = 0;
    for (; i + 1 < cnt; i += 2) {
        int s0 = __ldg(&g_srcs[beg + i]);
        int s1 = __ldg(&g_srcs[beg + i + 1]);
        float2 v0 = *(const float2*)(g_y + (size_t)s0 * 64 + lane * 2);
        float2 v1 = *(const float2*)(g_y + (size_t)s1 * 64 + lane * 2);
        acc.x += v0.x + v1.x;
        acc.y += v0.y + v1.y;
    }
    if (i < cnt) {
        int s0 = __ldg(&g_srcs[beg + i]);
        float2 v0 = *(const float2*)(g_y + (size_t)s0 * 64 + lane * 2);
        acc.x += v0.x;
        acc.y += v0.y;
    }

    float dv = g_dinv[node];
    float hx = fmaxf(fmaf(acc.x, dv, __ldg(&bias[lane * 2])), 0.f);
    float hy = fmaxf(fmaf(acc.y, dv, __ldg(&bias[lane * 2 + 1])), 0.f);

    if (!FINAL) {
        *(float2*)(g_h + (size_t)node * 64 + lane * 2) = make_float2(hx, hy);
    } else {
        float v = hx * __ldg(&Wfc[lane * 2]) + hy * __ldg(&Wfc[lane * 2 + 1]);
        #pragma unroll
        for (int o = 16; o; o >>= 1)
            v += __shfl_down_sync(0xffffffffu, v, o);
        if (lane == 0) {
            float z = v + __ldg(&bfc[0]);
            out[node] = 1.0f / (1.0f + expf(-z));
        }
    }
}

// ---------------- launch ----------------------------------------------------
extern "C" void kernel_launch(void* const* d_in, const int* in_sizes, int n_in,
                              void* d_out, int out_size) {
    const float* x   = (const float*)d_in[0];
    const void*  ei  = d_in[1];
    const float* W1  = (const float*)d_in[2];
    const float* b1  = (const float*)d_in[3];
    const float* W2  = (const float*)d_in[4];
    const float* b2  = (const float*)d_in[5];
    const float* Wfc = (const float*)d_in[6];
    const float* bfc = (const float*)d_in[7];
    float* out = (float*)d_out;

    int N = in_sizes[0] / 128;
    int E = in_sizes[1] / 2;
    if (N > MAXN) N = MAXN;
    if (E > MAXE) E = MAXE;

    const int TB = 256;
    int nb_N  = (N + TB - 1) / TB;
    int nb_E  = (E + TB - 1) / TB;
    int nb_GM = (N + 63) / 64;
    int nb_AG = (N + 7) / 8;
    int nblk  = (N + SCAN_TILE - 1) / SCAN_TILE;
    int nb_P3 = (N + TB * 4 - 1) / (TB * 4);

    detect_kernel<<<1, 32>>>((const int*)ei);
    zero_deg<<<nb_N, TB>>>(N);
    convert_kernel<<<nb_E, TB>>>(ei, E);
    scan_pass1<<<nblk, 1024>>>(N);
    scan_pass2<<<1, 64>>>(nblk);
    scan_pass3<<<nb_P3, TB>>>(N);
    place_kernel<<<nb_E, TB>>>(E);
    dinv_kernel<<<nb_N, TB>>>(N);

    // layer 1
    gemm_scale<128, false><<<nb_GM, 256>>>(x, W1, N);
    aggregate_kernel<false><<<nb_AG, 256>>>(b1, nullptr, nullptr, nullptr, N);

    // layer 2
    gemm_scale<64, true><<<nb_GM, 256>>>(nullptr, W2, N);
    aggregate_kernel<true><<<nb_AG, 256>>>(b2, Wfc, bfc, out, N);
}